// round 1
// baseline (speedup 1.0000x reference)
#include <cuda_runtime.h>

// Problem constants (fixed for this problem instance)
#define NN 200000
#define EE 1600000
#define UU 20000
#define DD 64
#define EPS 0.1f

// ---------------- scratch (static device allocations; allowed) ----------------
__device__ float g_x [(size_t)NN*DD];
__device__ float g_x1[(size_t)NN*DD];
__device__ float g_x2[(size_t)NN*DD];
__device__ float g_al[NN];
__device__ float g_ar[NN];
__device__ float g_dinv[NN];
__device__ int   g_deg[NN];
__device__ float g_x3[(size_t)UU*DD];
__device__ int   g_is32;   // 1 if integer inputs are int32, 0 if int64

__device__ __forceinline__ float lrelu(float v) { return v > 0.f ? v : 0.01f * v; }

// Load an index element from a buffer whose element type is int32 or int64
// depending on g_is32 (values always fit in int).
__device__ __forceinline__ int load_idx(const void* p, long long i) {
    if (g_is32) return ((const int*)p)[i];
    return (int)(((const long long*)p)[i]);
}

// ---------------- dtype detection ----------------
// Reference requests int64 indices but JAX may demote to int32 (no x64).
// True int64 index values are < 200000 < 2^32, so if ANY 8-byte word of
// edge_index is >= 2^32 the buffer must be packed int32 pairs.
__global__ void k_detect(const void* ei) {
    const unsigned long long* p = (const unsigned long long*)ei;
    int is32 = 0;
    for (int i = 0; i < 64; i++)
        if (p[i] > 0xFFFFFFFFull) is32 = 1;
    g_is32 = is32;
}

// ---------------- feature MLP: x = lrelu(concat(lrelu(num@Wn+bn), lrelu(cat@Wc+bc)) @ Wt + bt) ----------------
// 256 threads = 4 nodes x 64 dims per iteration; 8 iterations -> 32 nodes/block.
__global__ void k_feat(const float* __restrict__ numP, const float* __restrict__ catP,
                       const float* __restrict__ Wn, const float* __restrict__ bn,
                       const float* __restrict__ Wc, const float* __restrict__ bc,
                       const float* __restrict__ Wt, const float* __restrict__ bt) {
    __shared__ float sW[64 * 64];
    __shared__ float st[4][64];
    for (int i = threadIdx.x; i < 4096; i += 256) sW[i] = Wt[i];
    __syncthreads();
    int local = threadIdx.x >> 6;   // 0..3
    int d     = threadIdx.x & 63;   // 0..63
    for (int it = 0; it < 8; ++it) {
        int node = blockIdx.x * 32 + it * 4 + local;
        if (node < NN) {
            float t;
            if (d < 32) {
                float s = bn[d];
                const float* r = numP + (size_t)node * 20;
                #pragma unroll
                for (int k = 0; k < 20; k++) s += r[k] * Wn[k * 32 + d];
                t = lrelu(s);
            } else {
                int dd = d - 32;
                float s = bc[dd];
                const float* r = catP + (size_t)node * 12;
                #pragma unroll
                for (int k = 0; k < 12; k++) s += r[k] * Wc[k * 32 + dd];
                t = lrelu(s);
            }
            st[local][d] = t;
        }
        __syncthreads();
        if (node < NN) {
            float s = bt[d];
            #pragma unroll
            for (int k = 0; k < 64; k++) s += st[local][k] * sW[k * 64 + d];
            g_x[(size_t)node * 64 + d] = lrelu(s);
        }
        __syncthreads();
    }
}

// ---------------- degree / norm ----------------
__global__ void k_deg_init() {
    int i = blockIdx.x * blockDim.x + threadIdx.x;
    if (i < NN) g_deg[i] = 1;  // self loop
}
__global__ void k_deg_acc(const void* ei) {
    int e = blockIdx.x * blockDim.x + threadIdx.x;
    if (e >= EE) return;
    int d = load_idx(ei, (long long)EE + e);
    atomicAdd(&g_deg[d], 1);
}
__global__ void k_dinv() {
    int i = blockIdx.x * blockDim.x + threadIdx.x;
    if (i < NN) g_dinv[i] = rsqrtf((float)g_deg[i]);
}

// ---------------- per-node attention dots: al = h.att_l, ar = h.att_r ----------------
__global__ void k_dots(const float* __restrict__ h,
                       const float* __restrict__ attL, const float* __restrict__ attR) {
    int idx = blockIdx.x * blockDim.x + threadIdx.x;
    int node = idx >> 5;
    if (node >= NN) return;
    int lane = idx & 31;
    float2 hv = ((const float2*)(h + (size_t)node * 64))[lane];
    float a = hv.x * attL[2 * lane] + hv.y * attL[2 * lane + 1];
    float b = hv.x * attR[2 * lane] + hv.y * attR[2 * lane + 1];
    #pragma unroll
    for (int o = 16; o; o >>= 1) {
        a += __shfl_xor_sync(0xffffffffu, a, o);
        b += __shfl_xor_sync(0xffffffffu, b, o);
    }
    if (lane == 0) { g_al[node] = a; g_ar[node] = b; }
}

// ---------------- zero a float buffer ----------------
__global__ void k_zero(float* __restrict__ p, int n) {
    int i = blockIdx.x * blockDim.x + threadIdx.x;
    if (i < n) p[i] = 0.f;
}

// ---------------- edge scatter: agg[dst] += tanh(al[src]+ar[dst]) * dinv[src]*dinv[dst] * h[src] ----------------
// one warp per edge; float2 per lane; atomics compile to REDG (no return)
__global__ void k_edge(const void* __restrict__ ei, const float* __restrict__ h,
                       float* __restrict__ agg) {
    int idx = blockIdx.x * blockDim.x + threadIdx.x;
    int e = idx >> 5;
    if (e >= EE) return;
    int lane = idx & 31;
    int s = load_idx(ei, e);
    int d = load_idx(ei, (long long)EE + e);
    float alpha = 0.f;
    if (lane == 0)
        alpha = tanhf(g_al[s] + g_ar[d]) * g_dinv[s] * g_dinv[d];
    alpha = __shfl_sync(0xffffffffu, alpha, 0);
    float2 hv = ((const float2*)(h + (size_t)s * 64))[lane];
    float* o = agg + (size_t)d * 64 + lane * 2;
    atomicAdd(o,     hv.x * alpha);
    atomicAdd(o + 1, hv.y * alpha);
}

// ---------------- combine: agg += selfloop*h + eps*h0 ; optional smooth-abs ----------------
__global__ void k_combine(float* __restrict__ agg, const float* __restrict__ h,
                          const float* __restrict__ h0, int do_abs) {
    int idx = blockIdx.x * blockDim.x + threadIdx.x;
    if (idx >= NN * DD) return;
    int node = idx >> 6;
    float dv = g_dinv[node];
    float self = tanhf(g_al[node] + g_ar[node]) * dv * dv;
    float v = agg[idx] + self * h[idx] + EPS * h0[idx];
    if (do_abs) v = sqrtf(v * v + 1e-8f);
    agg[idx] = v;
}

// ---------------- ragged per-user segment sum via CSR offsets ----------------
__global__ void k_seg(const void* __restrict__ offs, const float* __restrict__ x2v,
                      float* __restrict__ x3v) {
    int idx = blockIdx.x * blockDim.x + threadIdx.x;
    int node = idx >> 5;
    if (node >= NN) return;
    int lane = idx & 31;
    int seg = 0;
    if (lane == 0) {
        // upper_bound over offs[0..UU] (UU+1 entries), seg = ub-1, clamped
        int lo = 0, hi = UU + 1;
        while (lo < hi) {
            int mid = (lo + hi) >> 1;
            if (load_idx(offs, mid) <= node) lo = mid + 1; else hi = mid;
        }
        seg = lo - 1;
        if (seg < 0) seg = 0;
        if (seg > UU - 1) seg = UU - 1;
    }
    seg = __shfl_sync(0xffffffffu, seg, 0);
    float2 v = ((const float2*)(x2v + (size_t)node * 64))[lane];
    float* o = x3v + (size_t)seg * 64 + lane * 2;
    atomicAdd(o,     v.x);
    atomicAdd(o + 1, v.y);
}

// ---------------- head: out = lrelu(x3[re] @ Wf + bf) @ Wl + bl ----------------
// one warp per user; lane j owns hidden dim j (32 dims)
__global__ void k_final(const void* __restrict__ re, const float* __restrict__ x3v,
                        const float* __restrict__ Wf, const float* __restrict__ bf,
                        const float* __restrict__ Wl, const float* __restrict__ bl,
                        float* __restrict__ out) {
    int idx = blockIdx.x * blockDim.x + threadIdx.x;
    int u = idx >> 5;
    if (u >= UU) return;
    int j = idx & 31;
    int g = load_idx(re, u);
    float2 gv = ((const float2*)(x3v + (size_t)g * 64))[j];
    float hj = bf[j];
    #pragma unroll
    for (int k = 0; k < 32; k++) {
        float a = __shfl_sync(0xffffffffu, gv.x, k);
        float b = __shfl_sync(0xffffffffu, gv.y, k);
        hj += a * Wf[(2 * k) * 32 + j] + b * Wf[(2 * k + 1) * 32 + j];
    }
    hj = lrelu(hj);
    float o0 = hj * Wl[j * 2];
    float o1 = hj * Wl[j * 2 + 1];
    #pragma unroll
    for (int o = 16; o; o >>= 1) {
        o0 += __shfl_xor_sync(0xffffffffu, o0, o);
        o1 += __shfl_xor_sync(0xffffffffu, o1, o);
    }
    if (j == 0) {
        out[(size_t)u * 2]     = o0 + bl[0];
        out[(size_t)u * 2 + 1] = o1 + bl[1];
    }
}

// ---------------- launch ----------------
extern "C" void kernel_launch(void* const* d_in, const int* in_sizes, int n_in,
                              void* d_out, int out_size) {
    const float* num_prop = (const float*)d_in[0];
    const float* cat_prop = (const float*)d_in[1];
    const void*  offs     = d_in[2];   // int64 or int32 (detected)
    const void*  ei       = d_in[3];
    const void*  re       = d_in[4];
    const float* W_num = (const float*)d_in[5];
    const float* b_num = (const float*)d_in[6];
    const float* W_cat = (const float*)d_in[7];
    const float* b_cat = (const float*)d_in[8];
    const float* W_tog = (const float*)d_in[9];
    const float* b_tog = (const float*)d_in[10];
    const float* att_l = (const float*)d_in[11];
    const float* att_r = (const float*)d_in[12];
    const float* W_f1  = (const float*)d_in[13];
    const float* b_f1  = (const float*)d_in[14];
    const float* W_lab = (const float*)d_in[15];
    const float* b_lab = (const float*)d_in[16];
    float* out = (float*)d_out;

    float *x, *x1, *x2, *x3;
    cudaGetSymbolAddress((void**)&x,  g_x);
    cudaGetSymbolAddress((void**)&x1, g_x1);
    cudaGetSymbolAddress((void**)&x2, g_x2);
    cudaGetSymbolAddress((void**)&x3, g_x3);

    const int T = 256;

    k_detect<<<1, 1>>>(ei);

    // features
    k_feat<<<(NN + 31) / 32, 256>>>(num_prop, cat_prop, W_num, b_num, W_cat, b_cat, W_tog, b_tog);

    // gcn_norm
    k_deg_init<<<(NN + T - 1) / T, T>>>();
    k_deg_acc<<<(EE + T - 1) / T, T>>>(ei);
    k_dinv<<<(NN + T - 1) / T, T>>>();

    // FAConv layer 1: x1 = faconv(x, x)
    k_dots<<<(NN * 32 + T - 1) / T, T>>>(x, att_l, att_r);
    k_zero<<<(NN * DD + T - 1) / T, T>>>(x1, NN * DD);
    k_edge<<<(EE * 32 + T - 1) / T, T>>>(ei, x, x1);
    k_combine<<<(NN * DD + T - 1) / T, T>>>(x1, x, x, 0);

    // FAConv layer 2: x2 = faconv(x1, x); smooth-abs
    k_dots<<<(NN * 32 + T - 1) / T, T>>>(x1, att_l, att_r);
    k_zero<<<(NN * DD + T - 1) / T, T>>>(x2, NN * DD);
    k_edge<<<(EE * 32 + T - 1) / T, T>>>(ei, x1, x2);
    k_combine<<<(NN * DD + T - 1) / T, T>>>(x2, x1, x, 1);

    // per-user segment sum
    k_zero<<<(UU * DD + T - 1) / T, T>>>(x3, UU * DD);
    k_seg<<<(NN * 32 + T - 1) / T, T>>>(offs, x2, x3);

    // head
    k_final<<<(UU * 32 + T - 1) / T, T>>>(re, x3, W_f1, b_f1, W_lab, b_lab, out);
}

// round 2
// speedup vs baseline: 1.9389x; 1.9389x over previous
#include <cuda_runtime.h>

// Problem constants (fixed for this problem instance)
#define NN 200000
#define EE 1600000
#define UU 20000
#define DD 64
#define EPS 0.1f

#define SCAN_BLK 2048                       // elements per scan block
#define NB ((NN + SCAN_BLK - 1) / SCAN_BLK) // 98 scan blocks

// ---------------- scratch (static device allocations; allowed) ----------------
__device__ float  g_x [(size_t)NN*DD];
__device__ float  g_x1[(size_t)NN*DD];
__device__ float  g_x2[(size_t)NN*DD];
__device__ float  g_dinv[NN];
__device__ int    g_deg[NN];        // in-degree + 1 (self loop)
__device__ int    g_offs[NN + 1];   // CSR row offsets (edges only, no self loops)
__device__ int    g_cursor[NN];
__device__ int    g_csr[EE];        // src node per CSR slot
__device__ int    g_bsum[NB];
__device__ float2 g_sd_a[NN];       // (al, dinv) per node, layer A
__device__ float2 g_sd_b[NN];       // layer B
__device__ float  g_ar_a[NN];
__device__ float  g_ar_b[NN];
__device__ float  g_x3[(size_t)UU*DD];
__device__ int    g_is32;           // 1 if integer inputs are int32, 0 if int64

__device__ __forceinline__ float lrelu(float v) { return v > 0.f ? v : 0.01f * v; }

__device__ __forceinline__ int load_idx(const void* p, long long i) {
    if (g_is32) return ((const int*)p)[i];
    return (int)(((const long long*)p)[i]);
}

// ---------------- dtype detection ----------------
// int64 index values here are < 200000 < 2^32, so any 8-byte word >= 2^32
// means the buffer is packed int32 pairs.
__global__ void k_detect(const void* ei) {
    const unsigned long long* p = (const unsigned long long*)ei;
    int is32 = 0;
    for (int i = 0; i < 64; i++)
        if (p[i] > 0xFFFFFFFFull) is32 = 1;
    g_is32 = is32;
}

// ---------------- feature MLP ----------------
__global__ void k_feat(const float* __restrict__ numP, const float* __restrict__ catP,
                       const float* __restrict__ Wn, const float* __restrict__ bn,
                       const float* __restrict__ Wc, const float* __restrict__ bc,
                       const float* __restrict__ Wt, const float* __restrict__ bt) {
    __shared__ float sW[64 * 64];
    __shared__ float st[4][64];
    for (int i = threadIdx.x; i < 4096; i += 256) sW[i] = Wt[i];
    __syncthreads();
    int local = threadIdx.x >> 6;
    int d     = threadIdx.x & 63;
    for (int it = 0; it < 8; ++it) {
        int node = blockIdx.x * 32 + it * 4 + local;
        if (node < NN) {
            float t;
            if (d < 32) {
                float s = bn[d];
                const float* r = numP + (size_t)node * 20;
                #pragma unroll
                for (int k = 0; k < 20; k++) s += r[k] * Wn[k * 32 + d];
                t = lrelu(s);
            } else {
                int dd = d - 32;
                float s = bc[dd];
                const float* r = catP + (size_t)node * 12;
                #pragma unroll
                for (int k = 0; k < 12; k++) s += r[k] * Wc[k * 32 + dd];
                t = lrelu(s);
            }
            st[local][d] = t;
        }
        __syncthreads();
        if (node < NN) {
            float s = bt[d];
            #pragma unroll
            for (int k = 0; k < 64; k++) s += st[local][k] * sW[k * 64 + d];
            g_x[(size_t)node * 64 + d] = lrelu(s);
        }
        __syncthreads();
    }
}

// ---------------- degree / norm ----------------
__global__ void k_deg_init() {
    int i = blockIdx.x * blockDim.x + threadIdx.x;
    if (i < NN) g_deg[i] = 1;  // self loop
}
__global__ void k_deg_acc(const void* ei) {
    int e = blockIdx.x * blockDim.x + threadIdx.x;
    if (e >= EE) return;
    int d = load_idx(ei, (long long)EE + e);
    atomicAdd(&g_deg[d], 1);
}
__global__ void k_dinv() {
    int i = blockIdx.x * blockDim.x + threadIdx.x;
    if (i < NN) g_dinv[i] = rsqrtf((float)g_deg[i]);
}

// ---------------- CSR offsets: exclusive scan of (deg-1) ----------------
__global__ void k_scan1() {
    __shared__ int ssum[256];
    int t = threadIdx.x;
    int base = blockIdx.x * SCAN_BLK + t * 8;
    int v[8];
    int sum = 0;
    #pragma unroll
    for (int k = 0; k < 8; k++) {
        int idx = base + k;
        int val = (idx < NN) ? (g_deg[idx] - 1) : 0;
        v[k] = sum;
        sum += val;
    }
    ssum[t] = sum;
    __syncthreads();
    #pragma unroll
    for (int off = 1; off < 256; off <<= 1) {
        int x = (t >= off) ? ssum[t - off] : 0;
        __syncthreads();
        ssum[t] += x;
        __syncthreads();
    }
    int texcl = ssum[t] - sum;   // exclusive prefix of this thread within block
    #pragma unroll
    for (int k = 0; k < 8; k++) {
        int idx = base + k;
        if (idx < NN) g_offs[idx] = texcl + v[k];
    }
    if (t == 255) g_bsum[blockIdx.x] = ssum[255];
}
__global__ void k_scan2() {
    __shared__ int s[128];
    int t = threadIdx.x;
    int val = (t < NB) ? g_bsum[t] : 0;
    s[t] = val;
    __syncthreads();
    #pragma unroll
    for (int off = 1; off < 128; off <<= 1) {
        int x = (t >= off) ? s[t - off] : 0;
        __syncthreads();
        s[t] += x;
        __syncthreads();
    }
    if (t < NB) g_bsum[t] = s[t] - val;   // exclusive
}
__global__ void k_scan3() {
    int i = blockIdx.x * blockDim.x + threadIdx.x;
    if (i < NN) {
        g_offs[i] += g_bsum[i / SCAN_BLK];
        g_cursor[i] = 0;
    }
    if (i == 0) g_offs[NN] = EE;
}

// ---------------- CSR scatter ----------------
__global__ void k_scatter(const void* __restrict__ ei) {
    int e = blockIdx.x * blockDim.x + threadIdx.x;
    if (e >= EE) return;
    int s = load_idx(ei, e);
    int d = load_idx(ei, (long long)EE + e);
    int pos = g_offs[d] + atomicAdd(&g_cursor[d], 1);
    g_csr[pos] = s;
}

// ---------------- per-node attention dots for layer A (from x) ----------------
__global__ void k_dots(const float* __restrict__ h,
                       const float* __restrict__ attL, const float* __restrict__ attR) {
    int idx = blockIdx.x * blockDim.x + threadIdx.x;
    int node = idx >> 5;
    if (node >= NN) return;
    int lane = idx & 31;
    float2 hv = ((const float2*)(h + (size_t)node * 64))[lane];
    float a = hv.x * attL[2 * lane] + hv.y * attL[2 * lane + 1];
    float b = hv.x * attR[2 * lane] + hv.y * attR[2 * lane + 1];
    #pragma unroll
    for (int o = 16; o; o >>= 1) {
        a += __shfl_xor_sync(0xffffffffu, a, o);
        b += __shfl_xor_sync(0xffffffffu, b, o);
    }
    if (lane == 0) {
        g_sd_a[node] = make_float2(a, g_dinv[node]);
        g_ar_a[node] = b;
    }
}

// ---------------- FAConv gather: one warp per dst node ----------------
// out[d] = sum_{e:dst=d} tanh(al[s]+ar[d])*dinv[s]*dinv[d]*h[s]
//          + tanh(al[d]+ar[d])*dinv[d]^2*h[d] + EPS*h0[d]
// Optionally smooth-abs, optionally compute next layer's dots from the output row.
template <int DO_ABS, int DO_DOTS>
__global__ void k_gather(const float* __restrict__ h, const float* __restrict__ h0,
                         const float2* __restrict__ sd_in, const float* __restrict__ ar_in,
                         float* __restrict__ out,
                         float2* __restrict__ sd_out, float* __restrict__ ar_out,
                         const float* __restrict__ attL, const float* __restrict__ attR) {
    int d = blockIdx.x * 8 + (threadIdx.x >> 5);
    if (d >= NN) return;
    int lane = threadIdx.x & 31;

    int start = g_offs[d];
    int end   = g_offs[d + 1];
    float2 sdd = sd_in[d];        // (al_d, dinv_d)
    float ar_d = ar_in[d];
    float dv_d = sdd.y;

    float2 acc = make_float2(0.f, 0.f);
    for (int base = start; base < end; base += 32) {
        int n = end - base; if (n > 32) n = 32;
        int s = 0; float alpha = 0.f;
        if (lane < n) {
            s = g_csr[base + lane];
            float2 sd = sd_in[s];
            alpha = tanhf(sd.x + ar_d) * sd.y * dv_d;
        }
        for (int j = 0; j < n; j++) {
            int   sj = __shfl_sync(0xffffffffu, s, j);
            float aj = __shfl_sync(0xffffffffu, alpha, j);
            float2 hv = ((const float2*)(h + (size_t)sj * 64))[lane];
            acc.x += aj * hv.x;
            acc.y += aj * hv.y;
        }
    }

    // self loop + eps*h0
    float aself = tanhf(sdd.x + ar_d) * dv_d * dv_d;
    float2 hd  = ((const float2*)(h  + (size_t)d * 64))[lane];
    float2 h0v = ((const float2*)(h0 + (size_t)d * 64))[lane];
    acc.x += aself * hd.x + EPS * h0v.x;
    acc.y += aself * hd.y + EPS * h0v.y;

    if (DO_ABS) {
        acc.x = sqrtf(acc.x * acc.x + 1e-8f);
        acc.y = sqrtf(acc.y * acc.y + 1e-8f);
    }
    ((float2*)(out + (size_t)d * 64))[lane] = acc;

    if (DO_DOTS) {
        float a = acc.x * attL[2 * lane] + acc.y * attL[2 * lane + 1];
        float b = acc.x * attR[2 * lane] + acc.y * attR[2 * lane + 1];
        #pragma unroll
        for (int o = 16; o; o >>= 1) {
            a += __shfl_xor_sync(0xffffffffu, a, o);
            b += __shfl_xor_sync(0xffffffffu, b, o);
        }
        if (lane == 0) {
            sd_out[d] = make_float2(a, dv_d);
            ar_out[d] = b;
        }
    }
}

// ---------------- per-user segment sum: direct gather from tweet_offsets CSR ----------------
__global__ void k_user(const void* __restrict__ offs, const float* __restrict__ x2v) {
    int u = blockIdx.x * 8 + (threadIdx.x >> 5);
    if (u >= UU) return;
    int lane = threadIdx.x & 31;
    int s0 = load_idx(offs, u);
    int s1 = load_idx(offs, u + 1);
    if (s0 < 0) s0 = 0;
    if (s1 > NN) s1 = NN;
    float2 acc = make_float2(0.f, 0.f);
    for (int r = s0; r < s1; r++) {
        float2 v = ((const float2*)(x2v + (size_t)r * 64))[lane];
        acc.x += v.x;
        acc.y += v.y;
    }
    ((float2*)(g_x3 + (size_t)u * 64))[lane] = acc;
}

// ---------------- head ----------------
__global__ void k_final(const void* __restrict__ re,
                        const float* __restrict__ Wf, const float* __restrict__ bf,
                        const float* __restrict__ Wl, const float* __restrict__ bl,
                        float* __restrict__ out) {
    int idx = blockIdx.x * blockDim.x + threadIdx.x;
    int u = idx >> 5;
    if (u >= UU) return;
    int j = idx & 31;
    int g = load_idx(re, u);
    float2 gv = ((const float2*)(g_x3 + (size_t)g * 64))[j];
    float hj = bf[j];
    #pragma unroll
    for (int k = 0; k < 32; k++) {
        float a = __shfl_sync(0xffffffffu, gv.x, k);
        float b = __shfl_sync(0xffffffffu, gv.y, k);
        hj += a * Wf[(2 * k) * 32 + j] + b * Wf[(2 * k + 1) * 32 + j];
    }
    hj = lrelu(hj);
    float o0 = hj * Wl[j * 2];
    float o1 = hj * Wl[j * 2 + 1];
    #pragma unroll
    for (int o = 16; o; o >>= 1) {
        o0 += __shfl_xor_sync(0xffffffffu, o0, o);
        o1 += __shfl_xor_sync(0xffffffffu, o1, o);
    }
    if (j == 0) {
        out[(size_t)u * 2]     = o0 + bl[0];
        out[(size_t)u * 2 + 1] = o1 + bl[1];
    }
}

// ---------------- launch ----------------
extern "C" void kernel_launch(void* const* d_in, const int* in_sizes, int n_in,
                              void* d_out, int out_size) {
    const float* num_prop = (const float*)d_in[0];
    const float* cat_prop = (const float*)d_in[1];
    const void*  offs     = d_in[2];
    const void*  ei       = d_in[3];
    const void*  re       = d_in[4];
    const float* W_num = (const float*)d_in[5];
    const float* b_num = (const float*)d_in[6];
    const float* W_cat = (const float*)d_in[7];
    const float* b_cat = (const float*)d_in[8];
    const float* W_tog = (const float*)d_in[9];
    const float* b_tog = (const float*)d_in[10];
    const float* att_l = (const float*)d_in[11];
    const float* att_r = (const float*)d_in[12];
    const float* W_f1  = (const float*)d_in[13];
    const float* b_f1  = (const float*)d_in[14];
    const float* W_lab = (const float*)d_in[15];
    const float* b_lab = (const float*)d_in[16];
    float* out = (float*)d_out;

    float *x, *x1, *x2;
    float2 *sda, *sdb;
    float *ara, *arb;
    cudaGetSymbolAddress((void**)&x,   g_x);
    cudaGetSymbolAddress((void**)&x1,  g_x1);
    cudaGetSymbolAddress((void**)&x2,  g_x2);
    cudaGetSymbolAddress((void**)&sda, g_sd_a);
    cudaGetSymbolAddress((void**)&sdb, g_sd_b);
    cudaGetSymbolAddress((void**)&ara, g_ar_a);
    cudaGetSymbolAddress((void**)&arb, g_ar_b);

    const int T = 256;

    k_detect<<<1, 1>>>(ei);

    // features
    k_feat<<<(NN + 31) / 32, 256>>>(num_prop, cat_prop, W_num, b_num, W_cat, b_cat, W_tog, b_tog);

    // degrees + dinv
    k_deg_init<<<(NN + T - 1) / T, T>>>();
    k_deg_acc<<<(EE + T - 1) / T, T>>>(ei);
    k_dinv<<<(NN + T - 1) / T, T>>>();

    // CSR build
    k_scan1<<<NB, 256>>>();
    k_scan2<<<1, 128>>>();
    k_scan3<<<(NN + T - 1) / T, T>>>();
    k_scatter<<<(EE + T - 1) / T, T>>>(ei);

    // layer-A dots from x
    k_dots<<<(NN * 32 + T - 1) / T, T>>>(x, att_l, att_r);

    // FAConv layer 1 (fused combine + next-layer dots)
    k_gather<0, 1><<<(NN + 7) / 8, 256>>>(x, x, sda, ara, x1, sdb, arb, att_l, att_r);

    // FAConv layer 2 (fused combine + smooth-abs)
    k_gather<1, 0><<<(NN + 7) / 8, 256>>>(x1, x, sdb, arb, x2, nullptr, nullptr, att_l, att_r);

    // per-user segment sum (direct CSR gather)
    k_user<<<(UU + 7) / 8, 256>>>(offs, x2);

    // head
    k_final<<<(UU * 32 + T - 1) / T, T>>>(re, W_f1, b_f1, W_lab, b_lab, out);
}

// round 3
// speedup vs baseline: 2.5419x; 1.3110x over previous
#include <cuda_runtime.h>

// Problem constants (fixed for this problem instance)
#define NN 200000
#define EE 1600000
#define UU 20000
#define DD 64
#define EPS 0.1f

#define SCAN_BLK 2048
#define NB ((NN + SCAN_BLK - 1) / SCAN_BLK)

// ---------------- scratch (static device allocations; allowed) ----------------
__device__ float  g_x [(size_t)NN*DD];
__device__ float  g_x1[(size_t)NN*DD];
__device__ float  g_x2[(size_t)NN*DD];
__device__ float  g_dinv[NN];
__device__ int    g_deg[NN];
__device__ int    g_offs[NN + 1];
__device__ int    g_cursor[NN];
__device__ int    g_csr[EE];
__device__ int    g_bsum[NB];
__device__ float2 g_sd_a[NN];   // (al, dinv)
__device__ float2 g_sd_b[NN];
__device__ float  g_ar_a[NN];
__device__ float  g_ar_b[NN];
__device__ float  g_x3[(size_t)UU*DD];
__device__ int    g_is32;

__device__ __forceinline__ float lrelu(float v) { return v > 0.f ? v : 0.01f * v; }

__device__ __forceinline__ int load_idx(const void* p, long long i) {
    if (g_is32) return ((const int*)p)[i];
    return (int)(((const long long*)p)[i]);
}

// ---------------- dtype detection ----------------
__global__ void k_detect(const void* ei) {
    const unsigned long long* p = (const unsigned long long*)ei;
    int is32 = 0;
    for (int i = 0; i < 64; i++)
        if (p[i] > 0xFFFFFFFFull) is32 = 1;
    g_is32 = is32;
}

// ---------------- degree / norm ----------------
__global__ void k_deg_init() {
    int i = blockIdx.x * blockDim.x + threadIdx.x;
    if (i < NN) g_deg[i] = 1;
}
__global__ void k_deg_acc(const void* ei) {
    int e = blockIdx.x * blockDim.x + threadIdx.x;
    if (e >= EE) return;
    int d = load_idx(ei, (long long)EE + e);
    atomicAdd(&g_deg[d], 1);
}
__global__ void k_dinv() {
    int i = blockIdx.x * blockDim.x + threadIdx.x;
    if (i < NN) g_dinv[i] = rsqrtf((float)g_deg[i]);
}

// ---------------- feature MLP, thread-per-node, fused attention dots ----------------
// x = lrelu(concat(lrelu(num@Wn+bn), lrelu(cat@Wc+bc)) @ Wt + bt)
// al = x . att_l ; ar = x . att_r  (stored with dinv for the gather kernels)
__global__ __launch_bounds__(256) void k_feat(
        const float* __restrict__ numP, const float* __restrict__ catP,
        const float* __restrict__ Wn, const float* __restrict__ bn,
        const float* __restrict__ Wc, const float* __restrict__ bc,
        const float* __restrict__ Wt, const float* __restrict__ bt,
        const float* __restrict__ attL, const float* __restrict__ attR) {
    __shared__ float4 sW[64 * 16];   // W_tog rows as float4 groups: sW[k*16+g]
    __shared__ float4 sWn[20 * 8];   // W_num: sWn[k*8+g]
    __shared__ float4 sWc[12 * 8];
    __shared__ float4 sbn[8], sbc[8], sbt[16], sL[16], sR[16];

    int t = threadIdx.x;
    for (int i = t; i < 64 * 16; i += 256) sW[i]  = ((const float4*)Wt)[i];
    for (int i = t; i < 20 * 8;  i += 256) sWn[i] = ((const float4*)Wn)[i];
    for (int i = t; i < 12 * 8;  i += 256) sWc[i] = ((const float4*)Wc)[i];
    if (t < 8)  sbn[t] = ((const float4*)bn)[t];
    if (t < 8)  sbc[t] = ((const float4*)bc)[t];
    if (t < 16) sbt[t] = ((const float4*)bt)[t];
    if (t < 16) sL[t]  = ((const float4*)attL)[t];
    if (t < 16) sR[t]  = ((const float4*)attR)[t];
    __syncthreads();

    int node = blockIdx.x * 256 + t;
    if (node >= NN) return;

    // ---- stage 1: st[64] in registers ----
    float stf[64];
    {
        float inf[20];
        const float4* nr = (const float4*)(numP + (size_t)node * 20);
        #pragma unroll
        for (int q = 0; q < 5; q++) {
            float4 v = __ldg(nr + q);
            inf[4*q] = v.x; inf[4*q+1] = v.y; inf[4*q+2] = v.z; inf[4*q+3] = v.w;
        }
        #pragma unroll
        for (int g = 0; g < 8; g++) {
            float4 a = sbn[g];
            #pragma unroll
            for (int k = 0; k < 20; k++) {
                float4 w = sWn[k * 8 + g];
                a.x += inf[k] * w.x; a.y += inf[k] * w.y;
                a.z += inf[k] * w.z; a.w += inf[k] * w.w;
            }
            stf[4*g]   = lrelu(a.x); stf[4*g+1] = lrelu(a.y);
            stf[4*g+2] = lrelu(a.z); stf[4*g+3] = lrelu(a.w);
        }
    }
    {
        float inf[12];
        const float4* cr = (const float4*)(catP + (size_t)node * 12);
        #pragma unroll
        for (int q = 0; q < 3; q++) {
            float4 v = __ldg(cr + q);
            inf[4*q] = v.x; inf[4*q+1] = v.y; inf[4*q+2] = v.z; inf[4*q+3] = v.w;
        }
        #pragma unroll
        for (int g = 0; g < 8; g++) {
            float4 a = sbc[g];
            #pragma unroll
            for (int k = 0; k < 12; k++) {
                float4 w = sWc[k * 8 + g];
                a.x += inf[k] * w.x; a.y += inf[k] * w.y;
                a.z += inf[k] * w.z; a.w += inf[k] * w.w;
            }
            stf[32+4*g]   = lrelu(a.x); stf[32+4*g+1] = lrelu(a.y);
            stf[32+4*g+2] = lrelu(a.z); stf[32+4*g+3] = lrelu(a.w);
        }
    }

    // ---- stage 2: 16 float4 output groups, W broadcast from smem ----
    float al = 0.f, ar = 0.f;
    float4* xrow = (float4*)(g_x + (size_t)node * 64);
    for (int g = 0; g < 16; g++) {
        float4 a = sbt[g];
        #pragma unroll
        for (int k = 0; k < 64; k++) {
            float4 w = sW[k * 16 + g];
            a.x += stf[k] * w.x; a.y += stf[k] * w.y;
            a.z += stf[k] * w.z; a.w += stf[k] * w.w;
        }
        a.x = lrelu(a.x); a.y = lrelu(a.y); a.z = lrelu(a.z); a.w = lrelu(a.w);
        float4 L = sL[g], R = sR[g];
        al += a.x * L.x + a.y * L.y + a.z * L.z + a.w * L.w;
        ar += a.x * R.x + a.y * R.y + a.z * R.z + a.w * R.w;
        xrow[g] = a;
    }
    g_sd_a[node] = make_float2(al, g_dinv[node]);
    g_ar_a[node] = ar;
}

// ---------------- CSR offsets: exclusive scan of (deg-1) ----------------
__global__ void k_scan1() {
    __shared__ int ssum[256];
    int t = threadIdx.x;
    int base = blockIdx.x * SCAN_BLK + t * 8;
    int v[8];
    int sum = 0;
    #pragma unroll
    for (int k = 0; k < 8; k++) {
        int idx = base + k;
        int val = (idx < NN) ? (g_deg[idx] - 1) : 0;
        v[k] = sum;
        sum += val;
    }
    ssum[t] = sum;
    __syncthreads();
    #pragma unroll
    for (int off = 1; off < 256; off <<= 1) {
        int x = (t >= off) ? ssum[t - off] : 0;
        __syncthreads();
        ssum[t] += x;
        __syncthreads();
    }
    int texcl = ssum[t] - sum;
    #pragma unroll
    for (int k = 0; k < 8; k++) {
        int idx = base + k;
        if (idx < NN) g_offs[idx] = texcl + v[k];
    }
    if (t == 255) g_bsum[blockIdx.x] = ssum[255];
}
__global__ void k_scan2() {
    __shared__ int s[128];
    int t = threadIdx.x;
    int val = (t < NB) ? g_bsum[t] : 0;
    s[t] = val;
    __syncthreads();
    #pragma unroll
    for (int off = 1; off < 128; off <<= 1) {
        int x = (t >= off) ? s[t - off] : 0;
        __syncthreads();
        s[t] += x;
        __syncthreads();
    }
    if (t < NB) g_bsum[t] = s[t] - val;
}
__global__ void k_scan3() {
    int i = blockIdx.x * blockDim.x + threadIdx.x;
    if (i < NN) {
        g_offs[i] += g_bsum[i / SCAN_BLK];
        g_cursor[i] = 0;
    }
    if (i == 0) g_offs[NN] = EE;
}

// ---------------- CSR scatter ----------------
__global__ void k_scatter(const void* __restrict__ ei) {
    int e = blockIdx.x * blockDim.x + threadIdx.x;
    if (e >= EE) return;
    int s = load_idx(ei, e);
    int d = load_idx(ei, (long long)EE + e);
    int pos = g_offs[d] + atomicAdd(&g_cursor[d], 1);
    g_csr[pos] = s;
}

// ---------------- FAConv gather: one warp per dst, half-warp x float4 ----------------
template <int DO_ABS, int DO_DOTS>
__global__ void k_gather(const float* __restrict__ h, const float* __restrict__ h0,
                         const float2* __restrict__ sd_in, const float* __restrict__ ar_in,
                         float* __restrict__ out,
                         float2* __restrict__ sd_out, float* __restrict__ ar_out,
                         const float* __restrict__ attL, const float* __restrict__ attR) {
    int d = blockIdx.x * 8 + (threadIdx.x >> 5);
    if (d >= NN) return;
    int lane = threadIdx.x & 31;
    int half = lane >> 4;
    int sub  = lane & 15;

    int start = g_offs[d];
    int end   = g_offs[d + 1];
    float2 sdd = __ldg(&sd_in[d]);
    float ar_d = __ldg(&ar_in[d]);
    float dv_d = sdd.y;

    float4 acc = make_float4(0.f, 0.f, 0.f, 0.f);
    for (int base = start; base < end; base += 32) {
        int n = end - base; if (n > 32) n = 32;
        int s = 0; float alpha = 0.f;
        if (lane < n) {
            s = __ldg(&g_csr[base + lane]);
            float2 sd = __ldg(&sd_in[s]);
            alpha = tanhf(sd.x + ar_d) * sd.y * dv_d;
        }
        int T = (n + 1) >> 1;
        for (int t = 0; t < T; t++) {
            int j = 2 * t + half;
            int   sj = __shfl_sync(0xffffffffu, s, j);
            float aj = __shfl_sync(0xffffffffu, alpha, j);
            if (j >= n) aj = 0.f;
            float4 hv = __ldg((const float4*)(h + (size_t)sj * 64) + sub);
            acc.x += aj * hv.x; acc.y += aj * hv.y;
            acc.z += aj * hv.z; acc.w += aj * hv.w;
        }
    }

    // combine the two half-warp partials
    acc.x += __shfl_xor_sync(0xffffffffu, acc.x, 16);
    acc.y += __shfl_xor_sync(0xffffffffu, acc.y, 16);
    acc.z += __shfl_xor_sync(0xffffffffu, acc.z, 16);
    acc.w += __shfl_xor_sync(0xffffffffu, acc.w, 16);

    if (half == 0) {
        float aself = tanhf(sdd.x + ar_d) * dv_d * dv_d;
        float4 hd  = __ldg((const float4*)(h  + (size_t)d * 64) + sub);
        float4 h0v = __ldg((const float4*)(h0 + (size_t)d * 64) + sub);
        acc.x += aself * hd.x + EPS * h0v.x;
        acc.y += aself * hd.y + EPS * h0v.y;
        acc.z += aself * hd.z + EPS * h0v.z;
        acc.w += aself * hd.w + EPS * h0v.w;
        if (DO_ABS) {
            acc.x = sqrtf(acc.x * acc.x + 1e-8f);
            acc.y = sqrtf(acc.y * acc.y + 1e-8f);
            acc.z = sqrtf(acc.z * acc.z + 1e-8f);
            acc.w = sqrtf(acc.w * acc.w + 1e-8f);
        }
        ((float4*)(out + (size_t)d * 64))[sub] = acc;

        if (DO_DOTS) {
            float4 L = __ldg((const float4*)attL + sub);
            float4 R = __ldg((const float4*)attR + sub);
            float a = acc.x * L.x + acc.y * L.y + acc.z * L.z + acc.w * L.w;
            float b = acc.x * R.x + acc.y * R.y + acc.z * R.z + acc.w * R.w;
            #pragma unroll
            for (int o = 8; o; o >>= 1) {
                a += __shfl_xor_sync(0x0000ffffu, a, o);
                b += __shfl_xor_sync(0x0000ffffu, b, o);
            }
            if (sub == 0) {
                sd_out[d] = make_float2(a, dv_d);
                ar_out[d] = b;
            }
        }
    }
}

// ---------------- per-user segment sum: direct CSR gather ----------------
__global__ void k_user(const void* __restrict__ offs, const float* __restrict__ x2v) {
    int u = blockIdx.x * 8 + (threadIdx.x >> 5);
    if (u >= UU) return;
    int lane = threadIdx.x & 31;
    int half = lane >> 4;
    int sub  = lane & 15;
    int s0 = load_idx(offs, u);
    int s1 = load_idx(offs, u + 1);
    if (s0 < 0) s0 = 0;
    if (s1 > NN) s1 = NN;
    float4 acc = make_float4(0.f, 0.f, 0.f, 0.f);
    for (int r = s0 + half; r < s1; r += 2) {
        float4 v = __ldg((const float4*)(x2v + (size_t)r * 64) + sub);
        acc.x += v.x; acc.y += v.y; acc.z += v.z; acc.w += v.w;
    }
    acc.x += __shfl_xor_sync(0xffffffffu, acc.x, 16);
    acc.y += __shfl_xor_sync(0xffffffffu, acc.y, 16);
    acc.z += __shfl_xor_sync(0xffffffffu, acc.z, 16);
    acc.w += __shfl_xor_sync(0xffffffffu, acc.w, 16);
    if (half == 0)
        ((float4*)(g_x3 + (size_t)u * 64))[sub] = acc;
}

// ---------------- head ----------------
__global__ void k_final(const void* __restrict__ re,
                        const float* __restrict__ Wf, const float* __restrict__ bf,
                        const float* __restrict__ Wl, const float* __restrict__ bl,
                        float* __restrict__ out) {
    int idx = blockIdx.x * blockDim.x + threadIdx.x;
    int u = idx >> 5;
    if (u >= UU) return;
    int j = idx & 31;
    int g = load_idx(re, u);
    float2 gv = ((const float2*)(g_x3 + (size_t)g * 64))[j];
    float hj = bf[j];
    #pragma unroll
    for (int k = 0; k < 32; k++) {
        float a = __shfl_sync(0xffffffffu, gv.x, k);
        float b = __shfl_sync(0xffffffffu, gv.y, k);
        hj += a * Wf[(2 * k) * 32 + j] + b * Wf[(2 * k + 1) * 32 + j];
    }
    hj = lrelu(hj);
    float o0 = hj * Wl[j * 2];
    float o1 = hj * Wl[j * 2 + 1];
    #pragma unroll
    for (int o = 16; o; o >>= 1) {
        o0 += __shfl_xor_sync(0xffffffffu, o0, o);
        o1 += __shfl_xor_sync(0xffffffffu, o1, o);
    }
    if (j == 0) {
        out[(size_t)u * 2]     = o0 + bl[0];
        out[(size_t)u * 2 + 1] = o1 + bl[1];
    }
}

// ---------------- launch ----------------
extern "C" void kernel_launch(void* const* d_in, const int* in_sizes, int n_in,
                              void* d_out, int out_size) {
    const float* num_prop = (const float*)d_in[0];
    const float* cat_prop = (const float*)d_in[1];
    const void*  offs     = d_in[2];
    const void*  ei       = d_in[3];
    const void*  re       = d_in[4];
    const float* W_num = (const float*)d_in[5];
    const float* b_num = (const float*)d_in[6];
    const float* W_cat = (const float*)d_in[7];
    const float* b_cat = (const float*)d_in[8];
    const float* W_tog = (const float*)d_in[9];
    const float* b_tog = (const float*)d_in[10];
    const float* att_l = (const float*)d_in[11];
    const float* att_r = (const float*)d_in[12];
    const float* W_f1  = (const float*)d_in[13];
    const float* b_f1  = (const float*)d_in[14];
    const float* W_lab = (const float*)d_in[15];
    const float* b_lab = (const float*)d_in[16];
    float* out = (float*)d_out;

    float *x, *x1, *x2;
    float2 *sda, *sdb;
    float *ara, *arb;
    cudaGetSymbolAddress((void**)&x,   g_x);
    cudaGetSymbolAddress((void**)&x1,  g_x1);
    cudaGetSymbolAddress((void**)&x2,  g_x2);
    cudaGetSymbolAddress((void**)&sda, g_sd_a);
    cudaGetSymbolAddress((void**)&sdb, g_sd_b);
    cudaGetSymbolAddress((void**)&ara, g_ar_a);
    cudaGetSymbolAddress((void**)&arb, g_ar_b);

    const int T = 256;

    k_detect<<<1, 1>>>(ei);

    // degrees + dinv first (k_feat consumes g_dinv)
    k_deg_init<<<(NN + T - 1) / T, T>>>();
    k_deg_acc<<<(EE + T - 1) / T, T>>>(ei);
    k_dinv<<<(NN + T - 1) / T, T>>>();

    // features + fused layer-A dots
    k_feat<<<(NN + 255) / 256, 256>>>(num_prop, cat_prop, W_num, b_num, W_cat, b_cat,
                                      W_tog, b_tog, att_l, att_r);

    // CSR build
    k_scan1<<<NB, 256>>>();
    k_scan2<<<1, 128>>>();
    k_scan3<<<(NN + T - 1) / T, T>>>();
    k_scatter<<<(EE + T - 1) / T, T>>>(ei);

    // FAConv layer 1 (fused combine + next-layer dots)
    k_gather<0, 1><<<(NN + 7) / 8, 256>>>(x, x, sda, ara, x1, sdb, arb, att_l, att_r);

    // FAConv layer 2 (fused combine + smooth-abs)
    k_gather<1, 0><<<(NN + 7) / 8, 256>>>(x1, x, sdb, arb, x2, nullptr, nullptr, att_l, att_r);

    // per-user segment sum
    k_user<<<(UU + 7) / 8, 256>>>(offs, x2);

    // head
    k_final<<<(UU * 32 + T - 1) / T, T>>>(re, W_f1, b_f1, W_lab, b_lab, out);
}